// round 12
// baseline (speedup 1.0000x reference)
#include <cuda_runtime.h>
#include <cstdint>
#include <cstddef>

// ============================================================================
// KMeansLoss on GB300 via legacy mma.sync — harness ptxas target is sm_103
// (no 'a'); tcgen05 unavailable.
//
// R12: INT8 IMMA experiment. R3..R11 established: legacy fp HMMA tensor-busy
// is a constant ~28us and the three best (structurally different) schedules
// all tie at 61.5us = busy/0.46 -> hardware rate ceiling for the legacy fp
// path. IMMA m16n8k32 (s8, s32 accum) is the one remaining instruction class
// with 2x MACs/inst on a historically separately-rated unit. Scale S=16
// (no clipping at 7.9 sigma), exact s32 accumulation; xsq/csq exact fp32.
//
// loss = ALPHA * mean_n sqrt(max( xsq[n] + min_k( csq[k] - 2*dot(x_n,c_k) ), 0))
//      dist^2 = xsq + csq - acc_s32 / 128        (dot = acc / (16*16))
// ============================================================================

namespace km {

constexpr int BATCH = 65536;
constexpr int KC    = 512;
constexpr int DIM   = 256;
constexpr float ALPHA = 0.05f;
constexpr float QS    = 16.0f;              // quantization scale
constexpr float FOLD  = 2.0f / (QS * QS);   // 2*dot = acc * FOLD = acc / 128

constexpr int M_CTA    = 128;
constexpr int NUM_CTAS = BATCH / M_CTA;     // 512
constexpr int THREADS  = 256;               // 8 warps, 16 rows each
constexpr int NCH      = 32;                // centers per chunk
constexpr int NCHUNKS  = KC / NCH;          // 16
constexpr int CHUNK_BYTES = NCH * DIM;      // 8192 (s8)
constexpr int NSTAGE   = 6;
constexpr int PDIST    = 3;

// ---- dynamic smem layout ----
constexpr int SM_CSQ  = 0;                  // 512 f = 2048 B
constexpr int SM_RED  = 2048;               // 8 f
constexpr int SM_MBF  = 2112;               // full mbars, 6 x 8B
constexpr int SM_MBE  = 2176;               // empty mbars, 6 x 8B
constexpr int SM_BB   = 4096;               // 6 x 8 KB B stages
constexpr int SMEM_TOTAL = SM_BB + NSTAGE * CHUNK_BYTES;   // 53248

// B fragments, ks-paired: [nbg(64)][ksp2(4)][lane(32)] x uint4 (s8 quads)
//  .x = b0(ks=2p)  : col (l>>2), k = 2p*32 + 4t..+3
//  .y = b1(ks=2p)  : col,        k = 2p*32 + 16 + 4t..+3
//  .z = b0(ks=2p+1), .w = b1(ks=2p+1)
__device__ uint4 g_Bfrag[(KC / 8) * 4 * 32];
__device__ float g_csq[KC];
__device__ float g_partials[NUM_CTAS];
__device__ unsigned int g_done;

// ---------------------------- helpers ---------------------------------------
__device__ __forceinline__ int q8(float f) {
    int i = __float2int_rn(f * QS);
    i = i < -127 ? -127 : (i > 127 ? 127 : i);
    return i;
}
__device__ __forceinline__ uint32_t pk_s8x4(float f0, float f1, float f2, float f3) {
    const int i0 = q8(f0), i1 = q8(f1), i2 = q8(f2), i3 = q8(f3);
    return (uint32_t)(i0 & 0xFF) | ((uint32_t)(i1 & 0xFF) << 8) |
           ((uint32_t)(i2 & 0xFF) << 16) | ((uint32_t)(i3 & 0xFF) << 24);
}
__device__ __forceinline__ void mma16832s8(int c[4], const uint32_t a[4],
                                           uint32_t b0, uint32_t b1) {
    asm volatile(
        "mma.sync.aligned.m16n8k32.row.col.s32.s8.s8.s32 "
        "{%0,%1,%2,%3}, {%4,%5,%6,%7}, {%8,%9}, {%0,%1,%2,%3};"
        : "+r"(c[0]), "+r"(c[1]), "+r"(c[2]), "+r"(c[3])
        : "r"(a[0]), "r"(a[1]), "r"(a[2]), "r"(a[3]), "r"(b0), "r"(b1));
}
__device__ __forceinline__ uint32_t smem_u32(const void* p) {
    return (uint32_t)__cvta_generic_to_shared(p);
}
__device__ __forceinline__ void cp16(uint32_t sdst, const void* gsrc) {
    asm volatile("cp.async.cg.shared.global [%0], [%1], 16;"
                 :: "r"(sdst), "l"(gsrc) : "memory");
}
__device__ __forceinline__ void cp_mbar_arrive_noinc(uint32_t mbar) {
    asm volatile("cp.async.mbarrier.arrive.noinc.shared::cta.b64 [%0];"
                 :: "r"(mbar) : "memory");
}
__device__ __forceinline__ void mbar_init(uint32_t a, uint32_t cnt) {
    asm volatile("mbarrier.init.shared.b64 [%0], %1;" :: "r"(a), "r"(cnt) : "memory");
}
__device__ __forceinline__ void mbar_arrive(uint32_t a) {
    asm volatile("mbarrier.arrive.shared.b64 _, [%0];" :: "r"(a) : "memory");
}
__device__ __forceinline__ void mbar_wait_parity(uint32_t mbar, uint32_t phase) {
    uint32_t done;
    do {
        asm volatile("{\n .reg .pred p;\n"
                     " mbarrier.try_wait.parity.acquire.cta.shared::cta.b64 p, [%1], %2, 0x989680;\n"
                     " selp.b32 %0, 1, 0, p;\n}"
                     : "=r"(done) : "r"(mbar), "r"(phase) : "memory");
    } while (!done);
}

// ------------------------- kernel 0: center convert -------------------------
// one warp per 8-center group; emits ks-paired uint4 s8 fragments + exact csq.
__global__ void __launch_bounds__(32) convert_centers(const float* __restrict__ ctr) {
    const int l   = threadIdx.x & 31;
    const int nbg = blockIdx.x;                 // 0..63
    const int n   = nbg * 8 + (l >> 2);
    const int t   = l & 3;
    const float* row = ctr + (size_t)n * DIM;
    float cs = 0.0f;
    #pragma unroll
    for (int p = 0; p < 4; ++p) {
        uint4 u;
        #pragma unroll
        for (int j = 0; j < 2; ++j) {
            const int k0 = (2 * p + j) * 32 + 4 * t;
            const float4 v0 = *reinterpret_cast<const float4*>(row + k0);
            const float4 v1 = *reinterpret_cast<const float4*>(row + k0 + 16);
            cs = fmaf(v0.x, v0.x, cs); cs = fmaf(v0.y, v0.y, cs);
            cs = fmaf(v0.z, v0.z, cs); cs = fmaf(v0.w, v0.w, cs);
            cs = fmaf(v1.x, v1.x, cs); cs = fmaf(v1.y, v1.y, cs);
            cs = fmaf(v1.z, v1.z, cs); cs = fmaf(v1.w, v1.w, cs);
            if (j == 0) {
                u.x = pk_s8x4(v0.x, v0.y, v0.z, v0.w);
                u.y = pk_s8x4(v1.x, v1.y, v1.z, v1.w);
            } else {
                u.z = pk_s8x4(v0.x, v0.y, v0.z, v0.w);
                u.w = pk_s8x4(v1.x, v1.y, v1.z, v1.w);
            }
        }
        g_Bfrag[(nbg * 4 + p) * 32 + l] = u;
    }
    cs += __shfl_xor_sync(0xFFFFFFFFu, cs, 1);
    cs += __shfl_xor_sync(0xFFFFFFFFu, cs, 2);
    if (t == 0) g_csq[n] = cs;
}

// ------------------------- kernel 1: main GEMM+min --------------------------
__global__ void __launch_bounds__(THREADS, 2)
kmeans_main(const float* __restrict__ emb, float* __restrict__ out) {
    extern __shared__ char smem[];
    const int tid = threadIdx.x;
    const int w   = tid >> 5;        // warp 0..7
    const int l   = tid & 31;
    const int t   = l & 3;
    const int m0  = blockIdx.x * M_CTA;
    float* csq_s = reinterpret_cast<float*>(smem + SM_CSQ);
    float* red_s = reinterpret_cast<float*>(smem + SM_RED);
    const uint32_t sbase = smem_u32(smem);

    // ---- init pipeline mbarriers + stage csq in smem ----
    if (tid == 0) {
        #pragma unroll
        for (int s = 0; s < NSTAGE; ++s) {
            mbar_init(sbase + SM_MBF + s * 8, THREADS);
            mbar_init(sbase + SM_MBE + s * 8, THREADS);
        }
    }
    if (tid < 128)
        reinterpret_cast<float4*>(csq_s)[tid] =
            reinterpret_cast<const float4*>(g_csq)[tid];
    __syncthreads();

    // ---- prefill stages 0..PDIST-1 (2 cp16/thread per 8KB chunk) ----
    #pragma unroll
    for (int s = 0; s < PDIST; ++s) {
        const char* src = reinterpret_cast<const char*>(g_Bfrag) + s * CHUNK_BYTES;
        const uint32_t dst = sbase + SM_BB + s * CHUNK_BYTES;
        #pragma unroll
        for (int i = 0; i < 2; ++i) {
            const int off = (i * THREADS + tid) * 16;
            cp16(dst + off, src + off);
        }
        cp_mbar_arrive_noinc(sbase + SM_MBF + s * 8);
    }

    // ---- A prologue: warp owns 16 rows; gmem -> 32 s8x4 fragments, exact xsq ----
    // a[ks][0] = row g,   k = ks*32 + 4t..+3 ; a[ks][1] = row g+8, same k
    // a[ks][2] = row g,   k+16..+19          ; a[ks][3] = row g+8, k+16..+19
    uint32_t a[8][4];
    float xs0 = 0.0f, xs1 = 0.0f;
    {
        const float* p0 = emb + (size_t)(m0 + w * 16 + (l >> 2)) * DIM + 4 * t;
        const float* p8 = p0 + (size_t)8 * DIM;
        #pragma unroll
        for (int ks = 0; ks < 8; ++ks) {
            const float4 v00 = *reinterpret_cast<const float4*>(p0 + ks * 32);
            const float4 v01 = *reinterpret_cast<const float4*>(p0 + ks * 32 + 16);
            const float4 v10 = *reinterpret_cast<const float4*>(p8 + ks * 32);
            const float4 v11 = *reinterpret_cast<const float4*>(p8 + ks * 32 + 16);
            xs0 = fmaf(v00.x, v00.x, xs0); xs0 = fmaf(v00.y, v00.y, xs0);
            xs0 = fmaf(v00.z, v00.z, xs0); xs0 = fmaf(v00.w, v00.w, xs0);
            xs0 = fmaf(v01.x, v01.x, xs0); xs0 = fmaf(v01.y, v01.y, xs0);
            xs0 = fmaf(v01.z, v01.z, xs0); xs0 = fmaf(v01.w, v01.w, xs0);
            xs1 = fmaf(v10.x, v10.x, xs1); xs1 = fmaf(v10.y, v10.y, xs1);
            xs1 = fmaf(v10.z, v10.z, xs1); xs1 = fmaf(v10.w, v10.w, xs1);
            xs1 = fmaf(v11.x, v11.x, xs1); xs1 = fmaf(v11.y, v11.y, xs1);
            xs1 = fmaf(v11.z, v11.z, xs1); xs1 = fmaf(v11.w, v11.w, xs1);
            a[ks][0] = pk_s8x4(v00.x, v00.y, v00.z, v00.w);
            a[ks][1] = pk_s8x4(v10.x, v10.y, v10.z, v10.w);
            a[ks][2] = pk_s8x4(v01.x, v01.y, v01.z, v01.w);
            a[ks][3] = pk_s8x4(v11.x, v11.y, v11.z, v11.w);
        }
    }
    xs0 += __shfl_xor_sync(0xFFFFFFFFu, xs0, 1);
    xs0 += __shfl_xor_sync(0xFFFFFFFFu, xs0, 2);
    xs1 += __shfl_xor_sync(0xFFFFFFFFu, xs1, 1);
    xs1 += __shfl_xor_sync(0xFFFFFFFFu, xs1, 2);

    float minv0 = 3.4e38f, minv1 = 3.4e38f;

    // ---- mainloop: 16 chunks, mbarrier pipeline, no __syncthreads ----
    int cst = 0, cph = 0;
    int pst = PDIST, pph = 1;

    #pragma unroll 1
    for (int ck = 0; ck < NCHUNKS; ++ck) {
        mbar_wait_parity(sbase + SM_MBF + cst * 8, (uint32_t)cph);

        const char* bb = smem + SM_BB + cst * CHUNK_BYTES;

        int acc[4][4];
        #pragma unroll
        for (int nb = 0; nb < 4; ++nb)
            #pragma unroll
            for (int c = 0; c < 4; ++c) acc[nb][c] = 0;

        #pragma unroll
        for (int p = 0; p < 4; ++p) {
            #pragma unroll
            for (int nb = 0; nb < 4; ++nb) {
                const uint4 b = *reinterpret_cast<const uint4*>(
                    bb + ((nb * 4 + p) * 32 + l) * 16);
                mma16832s8(acc[nb], a[2 * p],     b.x, b.y);
                mma16832s8(acc[nb], a[2 * p + 1], b.z, b.w);
            }
        }

        mbar_arrive(sbase + SM_MBE + cst * 8);

        const int cp = ck + PDIST;
        if (cp < NCHUNKS) {
            if (cp >= NSTAGE)
                mbar_wait_parity(sbase + SM_MBE + pst * 8, (uint32_t)pph);
            const char* src = reinterpret_cast<const char*>(g_Bfrag)
                              + cp * CHUNK_BYTES;
            const uint32_t dst = sbase + SM_BB + pst * CHUNK_BYTES;
            #pragma unroll
            for (int i = 0; i < 2; ++i) {
                const int off = (i * THREADS + tid) * 16;
                cp16(dst + off, src + off);
            }
            cp_mbar_arrive_noinc(sbase + SM_MBF + pst * 8);
            if (++pst == NSTAGE) { pst = 0; pph ^= 1; }
        }

        // fold (csq - acc/128) into running min
        #pragma unroll
        for (int nb = 0; nb < 4; ++nb) {
            const int col = ck * NCH + nb * 8 + 2 * t;
            const float cq0 = csq_s[col];
            const float cq1 = csq_s[col + 1];
            const float v0 = fminf(fmaf(-FOLD, (float)acc[nb][0], cq0),
                                   fmaf(-FOLD, (float)acc[nb][1], cq1));
            const float v1 = fminf(fmaf(-FOLD, (float)acc[nb][2], cq0),
                                   fmaf(-FOLD, (float)acc[nb][3], cq1));
            minv0 = fminf(minv0, v0);
            minv1 = fminf(minv1, v1);
        }

        if (++cst == NSTAGE) { cst = 0; cph ^= 1; }
    }

    // ---- epilogue: per-row min -> sqrt -> deterministic partial sum ----
    minv0 = fminf(minv0, __shfl_xor_sync(0xFFFFFFFFu, minv0, 1));
    minv0 = fminf(minv0, __shfl_xor_sync(0xFFFFFFFFu, minv0, 2));
    minv1 = fminf(minv1, __shfl_xor_sync(0xFFFFFFFFu, minv1, 1));
    minv1 = fminf(minv1, __shfl_xor_sync(0xFFFFFFFFu, minv1, 2));
    float s = 0.0f;
    if (t == 0)
        s = sqrtf(fmaxf(xs0 + minv0, 0.0f)) + sqrtf(fmaxf(xs1 + minv1, 0.0f));
    #pragma unroll
    for (int off = 16; off; off >>= 1) s += __shfl_down_sync(0xFFFFFFFFu, s, off);
    if (l == 0) red_s[w] = s;
    __syncthreads();

    __shared__ unsigned int is_last;
    if (tid == 0) {
        float tt = 0.0f;
        #pragma unroll
        for (int i = 0; i < 8; ++i) tt += red_s[i];
        g_partials[blockIdx.x] = tt;
        __threadfence();
        const unsigned int prev = atomicAdd(&g_done, 1u);
        is_last = (prev == (unsigned)(NUM_CTAS - 1)) ? 1u : 0u;
    }
    __syncthreads();

    if (is_last) {
        __threadfence();
        float v = g_partials[tid] + g_partials[tid + 256];
        #pragma unroll
        for (int off = 16; off; off >>= 1) v += __shfl_down_sync(0xFFFFFFFFu, v, off);
        if (l == 0) red_s[w] = v;
        __syncthreads();
        if (tid == 0) {
            float tt = 0.0f;
            #pragma unroll
            for (int i = 0; i < 8; ++i) tt += red_s[i];
            out[0] = tt * (ALPHA / (float)BATCH);
            g_done = 0u;                 // reset for next graph replay
            __threadfence();
        }
    }
}

} // namespace km

extern "C" void kernel_launch(void* const* d_in, const int* in_sizes, int n_in,
                              void* d_out, int out_size) {
    const float* emb = (const float*)d_in[0];   // [65536, 256] fp32
    const float* ctr = (const float*)d_in[1];   // [512, 256]  fp32
    float* out = (float*)d_out;                 // scalar fp32

    cudaFuncSetAttribute(km::kmeans_main,
                         cudaFuncAttributeMaxDynamicSharedMemorySize, km::SMEM_TOTAL);

    km::convert_centers<<<64, 32>>>(ctr);
    km::kmeans_main<<<km::NUM_CTAS, km::THREADS, km::SMEM_TOTAL>>>(emb, out);
}

// round 13
// speedup vs baseline: 2.4298x; 2.4298x over previous
#include <cuda_runtime.h>
#include <cuda_fp16.h>
#include <cstdint>
#include <cstddef>

// ============================================================================
// KMeansLoss on GB300 via legacy mma.sync (HMMA fp16-accum) — harness ptxas
// target is sm_103 (no 'a'); tcgen05 unavailable.
//
// R13: SINGLE-LAUNCH version of R10 (best, 61.5us). R12 confirmed the legacy
// HMMA issue floor: 28.3K HMMA/SM x rt~16cyc/SMSP = 61.7us — we are AT the
// hardware rate cap, so the only remaining cycles are the separate
// convert_centers launch (~2us). Fused here: warp 0 of CTAs 0..63 converts
// its 8-center fragment group BEFORE its A prologue and releases a global
// flag; all CTAs consume B only after the flag (checked after the A
// prologue, which fully hides conversion). Deterministic last-CTA finalize
// resets the counters for graph replay.
//
// loss = ALPHA * mean_n sqrt(max( xsq[n] + min_k( csq[k] - 2*dot(x_n,c_k) ), 0))
// ============================================================================

namespace km {

constexpr int BATCH = 65536;
constexpr int KC    = 512;
constexpr int DIM   = 256;
constexpr float ALPHA = 0.05f;

constexpr int M_CTA    = 128;
constexpr int NUM_CTAS = BATCH / M_CTA;     // 512
constexpr int THREADS  = 256;               // 8 warps, 16 rows each
constexpr int NCH      = 32;                // centers per chunk
constexpr int NCHUNKS  = KC / NCH;          // 16
constexpr int CHUNK_BYTES = NCH * DIM * 2;  // 16384
constexpr int NSTAGE   = 6;
constexpr int PDIST    = 3;
constexpr int NCONV    = 64;                // converter CTAs (warp 0 each)

// ---- dynamic smem layout ----
constexpr int SM_CSQ  = 0;                  // 512 f = 2048 B
constexpr int SM_RED  = 2048;               // 8 f
constexpr int SM_MBF  = 2112;               // full mbars, 6 x 8B
constexpr int SM_MBE  = 2176;               // empty mbars, 6 x 8B
constexpr int SM_BB   = 4096;               // 6 x 16 KB B stages
constexpr int SMEM_TOTAL = SM_BB + NSTAGE * CHUNK_BYTES;   // 102400 (2 CTAs/SM)

// B fragments, ks-paired: [nbg(64)][ksp(8)][lane(32)] x uint4 (fp16 pairs)
__device__ uint4 g_Bfrag[(KC / 8) * 8 * 32];
__device__ float g_csq[KC];
__device__ float g_partials[NUM_CTAS];
__device__ unsigned int g_flag;             // converter-done counter
__device__ unsigned int g_done;             // finished-CTA counter

// ---------------------------- helpers ---------------------------------------
__device__ __forceinline__ uint32_t pk_f16x2(float lo, float hi) {
    const __half2 h = __floats2half2_rn(lo, hi);
    return *reinterpret_cast<const uint32_t*>(&h);
}
__device__ __forceinline__ void mma16816h(uint32_t c[2], const uint32_t a[4],
                                          uint32_t b0, uint32_t b1) {
    asm volatile(
        "mma.sync.aligned.m16n8k16.row.col.f16.f16.f16.f16 "
        "{%0,%1}, {%2,%3,%4,%5}, {%6,%7}, {%0,%1};"
        : "+r"(c[0]), "+r"(c[1])
        : "r"(a[0]), "r"(a[1]), "r"(a[2]), "r"(a[3]), "r"(b0), "r"(b1));
}
__device__ __forceinline__ uint32_t smem_u32(const void* p) {
    return (uint32_t)__cvta_generic_to_shared(p);
}
__device__ __forceinline__ void cp16(uint32_t sdst, const void* gsrc) {
    asm volatile("cp.async.cg.shared.global [%0], [%1], 16;"
                 :: "r"(sdst), "l"(gsrc) : "memory");
}
__device__ __forceinline__ void cp_mbar_arrive_noinc(uint32_t mbar) {
    asm volatile("cp.async.mbarrier.arrive.noinc.shared::cta.b64 [%0];"
                 :: "r"(mbar) : "memory");
}
__device__ __forceinline__ void mbar_init(uint32_t a, uint32_t cnt) {
    asm volatile("mbarrier.init.shared.b64 [%0], %1;" :: "r"(a), "r"(cnt) : "memory");
}
__device__ __forceinline__ void mbar_arrive(uint32_t a) {
    asm volatile("mbarrier.arrive.shared.b64 _, [%0];" :: "r"(a) : "memory");
}
__device__ __forceinline__ void mbar_wait_parity(uint32_t mbar, uint32_t phase) {
    uint32_t done;
    do {
        asm volatile("{\n .reg .pred p;\n"
                     " mbarrier.try_wait.parity.acquire.cta.shared::cta.b64 p, [%1], %2, 0x989680;\n"
                     " selp.b32 %0, 1, 0, p;\n}"
                     : "=r"(done) : "r"(mbar), "r"(phase) : "memory");
    } while (!done);
}
__device__ __forceinline__ uint32_t ld_acquire(const unsigned int* p) {
    uint32_t v;
    asm volatile("ld.acquire.gpu.global.u32 %0, [%1];" : "=r"(v) : "l"(p) : "memory");
    return v;
}

// ------------------------------ fused kernel --------------------------------
__global__ void __launch_bounds__(THREADS, 2)
kmeans_main(const float* __restrict__ emb, const float* __restrict__ ctr,
            float* __restrict__ out) {
    extern __shared__ char smem[];
    const int tid = threadIdx.x;
    const int w   = tid >> 5;        // warp 0..7
    const int l   = tid & 31;
    const int m0  = blockIdx.x * M_CTA;
    float* csq_s = reinterpret_cast<float*>(smem + SM_CSQ);
    float* red_s = reinterpret_cast<float*>(smem + SM_RED);
    const uint32_t sbase = smem_u32(smem);

    if (tid == 0) {
        #pragma unroll
        for (int s = 0; s < NSTAGE; ++s) {
            mbar_init(sbase + SM_MBF + s * 8, THREADS);
            mbar_init(sbase + SM_MBE + s * 8, THREADS);
        }
    }

    // ---- phase 0: warp 0 of CTAs 0..63 converts its 8-center group ----
    if (blockIdx.x < NCONV && w == 0) {
        const int nbg = blockIdx.x;
        const int n   = nbg * 8 + (l >> 2);
        const float* row = ctr + (size_t)n * DIM;
        float cs = 0.0f;
        #pragma unroll
        for (int ksp = 0; ksp < 8; ++ksp) {
            uint4 u;
            #pragma unroll
            for (int j = 0; j < 2; ++j) {
                const int k0 = (ksp * 2 + j) * 16 + 2 * (l & 3);
                const float2 v0 = *reinterpret_cast<const float2*>(row + k0);
                const float2 v1 = *reinterpret_cast<const float2*>(row + k0 + 8);
                cs = fmaf(v0.x, v0.x, cs); cs = fmaf(v0.y, v0.y, cs);
                cs = fmaf(v1.x, v1.x, cs); cs = fmaf(v1.y, v1.y, cs);
                if (j == 0) { u.x = pk_f16x2(v0.x, v0.y); u.y = pk_f16x2(v1.x, v1.y); }
                else        { u.z = pk_f16x2(v0.x, v0.y); u.w = pk_f16x2(v1.x, v1.y); }
            }
            g_Bfrag[(nbg * 8 + ksp) * 32 + l] = u;
        }
        cs += __shfl_xor_sync(0xFFFFFFFFu, cs, 1);
        cs += __shfl_xor_sync(0xFFFFFFFFu, cs, 2);
        if ((l & 3) == 0) g_csq[n] = cs;
        __threadfence();                       // release g_Bfrag + g_csq
        if (l == 0) atomicAdd(&g_flag, 1u);
    }

    // ---- phase 1: A prologue (independent of B) — hides conversion ----
    uint32_t a[16][4];
    float xs0 = 0.0f, xs1 = 0.0f;
    {
        const float* p0 = emb + (size_t)(m0 + w * 16 + (l >> 2)) * DIM + 2 * (l & 3);
        const float* p8 = p0 + (size_t)8 * DIM;
        #pragma unroll
        for (int ks = 0; ks < 16; ++ks) {
            const float2 v00 = *reinterpret_cast<const float2*>(p0 + ks * 16);
            const float2 v01 = *reinterpret_cast<const float2*>(p0 + ks * 16 + 8);
            const float2 v10 = *reinterpret_cast<const float2*>(p8 + ks * 16);
            const float2 v11 = *reinterpret_cast<const float2*>(p8 + ks * 16 + 8);
            xs0 = fmaf(v00.x, v00.x, xs0); xs0 = fmaf(v00.y, v00.y, xs0);
            xs0 = fmaf(v01.x, v01.x, xs0); xs0 = fmaf(v01.y, v01.y, xs0);
            xs1 = fmaf(v10.x, v10.x, xs1); xs1 = fmaf(v10.y, v10.y, xs1);
            xs1 = fmaf(v11.x, v11.x, xs1); xs1 = fmaf(v11.y, v11.y, xs1);
            a[ks][0] = pk_f16x2(v00.x, v00.y);
            a[ks][1] = pk_f16x2(v10.x, v10.y);
            a[ks][2] = pk_f16x2(v01.x, v01.y);
            a[ks][3] = pk_f16x2(v11.x, v11.y);
        }
    }
    xs0 += __shfl_xor_sync(0xFFFFFFFFu, xs0, 1);
    xs0 += __shfl_xor_sync(0xFFFFFFFFu, xs0, 2);
    xs1 += __shfl_xor_sync(0xFFFFFFFFu, xs1, 1);
    xs1 += __shfl_xor_sync(0xFFFFFFFFu, xs1, 2);

    // ---- wait for all converters, then consume B: csq + prefill ----
    if (tid == 0) {
        while (ld_acquire(&g_flag) < (unsigned)NCONV) {
            asm volatile("nanosleep.u32 64;");
        }
    }
    __syncthreads();   // flag + mbar-init visibility to all warps

    if (tid < 128)
        reinterpret_cast<float4*>(csq_s)[tid] =
            reinterpret_cast<const float4*>(g_csq)[tid];
    #pragma unroll
    for (int s = 0; s < PDIST; ++s) {
        const char* src = reinterpret_cast<const char*>(g_Bfrag) + s * CHUNK_BYTES;
        const uint32_t dst = sbase + SM_BB + s * CHUNK_BYTES;
        #pragma unroll
        for (int i = 0; i < 4; ++i) {
            const int off = (i * THREADS + tid) * 16;
            cp16(dst + off, src + off);
        }
        cp_mbar_arrive_noinc(sbase + SM_MBF + s * 8);
    }
    __syncthreads();   // csq_s visible before any fold reads it

    float minv0 = 3.4e38f, minv1 = 3.4e38f;

    // ---- mainloop: 16 chunks, mbarrier pipeline, no __syncthreads ----
    int cst = 0, cph = 0;
    int pst = PDIST, pph = 1;

    #pragma unroll 1
    for (int ck = 0; ck < NCHUNKS; ++ck) {
        mbar_wait_parity(sbase + SM_MBF + cst * 8, (uint32_t)cph);

        const char* bb = smem + SM_BB + cst * CHUNK_BYTES;

        uint32_t acc[4][2];
        #pragma unroll
        for (int nb = 0; nb < 4; ++nb) { acc[nb][0] = 0u; acc[nb][1] = 0u; }

        #pragma unroll
        for (int ksp = 0; ksp < 8; ++ksp) {
            #pragma unroll
            for (int nb = 0; nb < 4; ++nb) {
                const uint4 b = *reinterpret_cast<const uint4*>(
                    bb + ((nb * 8 + ksp) * 32 + l) * 16);
                mma16816h(acc[nb], a[2 * ksp],     b.x, b.y);
                mma16816h(acc[nb], a[2 * ksp + 1], b.z, b.w);
            }
        }

        mbar_arrive(sbase + SM_MBE + cst * 8);

        const int cp = ck + PDIST;
        if (cp < NCHUNKS) {
            if (cp >= NSTAGE)
                mbar_wait_parity(sbase + SM_MBE + pst * 8, (uint32_t)pph);
            const char* src = reinterpret_cast<const char*>(g_Bfrag)
                              + cp * CHUNK_BYTES;
            const uint32_t dst = sbase + SM_BB + pst * CHUNK_BYTES;
            #pragma unroll
            for (int i = 0; i < 4; ++i) {
                const int off = (i * THREADS + tid) * 16;
                cp16(dst + off, src + off);
            }
            cp_mbar_arrive_noinc(sbase + SM_MBF + pst * 8);
            if (++pst == NSTAGE) { pst = 0; pph ^= 1; }
        }

        // fold (csq - 2*dot) into running min (unpack f16x2 accumulators)
        #pragma unroll
        for (int nb = 0; nb < 4; ++nb) {
            const int col = ck * NCH + nb * 8 + 2 * (l & 3);
            const float cq0 = csq_s[col];
            const float cq1 = csq_s[col + 1];
            const float2 f0 = __half22float2(
                *reinterpret_cast<const __half2*>(&acc[nb][0]));   // row r
            const float2 f1 = __half22float2(
                *reinterpret_cast<const __half2*>(&acc[nb][1]));   // row r+8
            const float v0 = fminf(fmaf(-2.0f, f0.x, cq0),
                                   fmaf(-2.0f, f0.y, cq1));
            const float v1 = fminf(fmaf(-2.0f, f1.x, cq0),
                                   fmaf(-2.0f, f1.y, cq1));
            minv0 = fminf(minv0, v0);
            minv1 = fminf(minv1, v1);
        }

        if (++cst == NSTAGE) { cst = 0; cph ^= 1; }
    }

    // ---- epilogue: per-row min -> sqrt -> deterministic partial sum ----
    minv0 = fminf(minv0, __shfl_xor_sync(0xFFFFFFFFu, minv0, 1));
    minv0 = fminf(minv0, __shfl_xor_sync(0xFFFFFFFFu, minv0, 2));
    minv1 = fminf(minv1, __shfl_xor_sync(0xFFFFFFFFu, minv1, 1));
    minv1 = fminf(minv1, __shfl_xor_sync(0xFFFFFFFFu, minv1, 2));
    float s = 0.0f;
    if ((l & 3) == 0)
        s = sqrtf(fmaxf(xs0 + minv0, 0.0f)) + sqrtf(fmaxf(xs1 + minv1, 0.0f));
    #pragma unroll
    for (int off = 16; off; off >>= 1) s += __shfl_down_sync(0xFFFFFFFFu, s, off);
    if (l == 0) red_s[w] = s;
    __syncthreads();

    __shared__ unsigned int is_last;
    if (tid == 0) {
        float t = 0.0f;
        #pragma unroll
        for (int i = 0; i < 8; ++i) t += red_s[i];
        g_partials[blockIdx.x] = t;
        __threadfence();
        const unsigned int prev = atomicAdd(&g_done, 1u);
        is_last = (prev == (unsigned)(NUM_CTAS - 1)) ? 1u : 0u;
    }
    __syncthreads();

    if (is_last) {
        __threadfence();
        float v = g_partials[tid] + g_partials[tid + 256];
        #pragma unroll
        for (int off = 16; off; off >>= 1) v += __shfl_down_sync(0xFFFFFFFFu, v, off);
        if (l == 0) red_s[w] = v;
        __syncthreads();
        if (tid == 0) {
            float t = 0.0f;
            #pragma unroll
            for (int i = 0; i < 8; ++i) t += red_s[i];
            out[0] = t * (ALPHA / (float)BATCH);
            g_done = 0u;                 // reset for next graph replay
            g_flag = 0u;
            __threadfence();
        }
    }
}

} // namespace km

extern "C" void kernel_launch(void* const* d_in, const int* in_sizes, int n_in,
                              void* d_out, int out_size) {
    const float* emb = (const float*)d_in[0];   // [65536, 256] fp32
    const float* ctr = (const float*)d_in[1];   // [512, 256]  fp32
    float* out = (float*)d_out;                 // scalar fp32

    cudaFuncSetAttribute(km::kmeans_main,
                         cudaFuncAttributeMaxDynamicSharedMemorySize, km::SMEM_TOTAL);

    km::kmeans_main<<<km::NUM_CTAS, km::THREADS, km::SMEM_TOTAL>>>(emb, ctr, out);
}